// round 2
// baseline (speedup 1.0000x reference)
#include <cuda_runtime.h>
#include <cuda_bf16.h>
#include <math.h>

#define NN 10000
#define EE 50000
#define EA 60000      // E + N self loops
#define ED 16
#define KBI 272
#define CBI 4352      // 272*16
#define HMAX 512

// ---------------- scratch (static device globals; no runtime alloc) ----------------
__device__ float g_h1[NN * HMAX];
__device__ float g_h2[NN * HMAX];
__device__ float g_xl[NN * HMAX];
__device__ float g_xr[NN * HMAX];
__device__ float g_alpha[EA];
__device__ float g_ex[EA];
__device__ unsigned g_amax[NN];
__device__ float g_den[NN];
__device__ float g_cnt[NN];
__device__ float g_msum[NN * ED];
__device__ float g_mean[NN * ED];
__device__ float g_U[HMAX * CBI];
__device__ float g_V[HMAX * CBI];
__device__ float g_A[(size_t)NN * CBI];
__device__ float g_B[(size_t)NN * CBI];

// ---------------- helpers ----------------
__device__ __forceinline__ unsigned fkey(float f) {
    unsigned u = __float_as_uint(f);
    return (u & 0x80000000u) ? ~u : (u | 0x80000000u);
}
__device__ __forceinline__ float funkey(unsigned k) {
    return (k & 0x80000000u) ? __uint_as_float(k ^ 0x80000000u) : __uint_as_float(~k);
}

// ---------------- edge_attr mean per dst (self-loop fill 'mean') ----------------
__global__ void k_count(const int* __restrict__ dst, const float* __restrict__ ea) {
    int idx = blockIdx.x * blockDim.x + threadIdx.x;
    if (idx >= EE * ED) return;
    int e = idx >> 4, j = idx & 15;
    int d = dst[e];
    atomicAdd(&g_msum[d * ED + j], ea[idx]);
    if (j == 0) atomicAdd(&g_cnt[d], 1.0f);
}
__global__ void k_mean() {
    int idx = blockIdx.x * blockDim.x + threadIdx.x;
    if (idx >= NN * ED) return;
    g_mean[idx] = g_msum[idx] / fmaxf(g_cnt[idx >> 4], 1.0f);
}

// ---------------- tiled SGEMM: C[M,Nn] = A[M,K] * B[K,Nn], row-major ----------------
// BM=BN=128, BK=8, TM=TN=8, 256 threads. Nn multiple of 128, K multiple of 8.
__global__ void sgemm128(const float* __restrict__ A, const float* __restrict__ B,
                         float* __restrict__ C, int M, int Nn, int K) {
    __shared__ float As[8][128];
    __shared__ float Bs[8][128];
    int tid = threadIdx.x;
    int brow = blockIdx.y * 128;
    int bcol = blockIdx.x * 128;
    int tr = (tid / 16) * 8;
    int tc = (tid % 16) * 8;
    float acc[8][8];
#pragma unroll
    for (int i = 0; i < 8; i++)
#pragma unroll
        for (int j = 0; j < 8; j++) acc[i][j] = 0.0f;

    int arow = tid >> 1;
    int acol = (tid & 1) * 4;
    int brr = tid >> 5;
    int bcc = (tid & 31) * 4;
    bool a_ok = (brow + arow) < M;
    const float* Aptr = A + (size_t)(brow + arow) * K + acol;

    for (int k0 = 0; k0 < K; k0 += 8) {
        float4 av = a_ok ? *(const float4*)(Aptr + k0) : make_float4(0.f, 0.f, 0.f, 0.f);
        As[acol + 0][arow] = av.x;
        As[acol + 1][arow] = av.y;
        As[acol + 2][arow] = av.z;
        As[acol + 3][arow] = av.w;
        float4 bv = *(const float4*)(B + (size_t)(k0 + brr) * Nn + bcol + bcc);
        *(float4*)&Bs[brr][bcc] = bv;
        __syncthreads();
#pragma unroll
        for (int kk = 0; kk < 8; kk++) {
            float a[8], b[8];
#pragma unroll
            for (int i = 0; i < 8; i++) a[i] = As[kk][tr + i];
#pragma unroll
            for (int j = 0; j < 8; j++) b[j] = Bs[kk][tc + j];
#pragma unroll
            for (int i = 0; i < 8; i++)
#pragma unroll
                for (int j = 0; j < 8; j++) acc[i][j] += a[i] * b[j];
        }
        __syncthreads();
    }
#pragma unroll
    for (int i = 0; i < 8; i++) {
        int r = brow + tr + i;
        if (r < M) {
#pragma unroll
            for (int j = 0; j < 8; j++) C[(size_t)r * Nn + bcol + tc + j] = acc[i][j];
        }
    }
}

// ---------------- GAT per-edge attention score (one warp per augmented edge) ----------------
__global__ void k_alpha(const int* __restrict__ src, const int* __restrict__ dst,
                        const float* __restrict__ ea,
                        const float* __restrict__ xl, const float* __restrict__ xr,
                        const float* __restrict__ We, const float* __restrict__ att,
                        int dout) {
    int e = (blockIdx.x * blockDim.x + threadIdx.x) >> 5;
    int lane = threadIdx.x & 31;
    if (e >= EA) return;
    int s, d;
    const float* eap;
    if (e < EE) { s = src[e]; d = dst[e]; eap = ea + (size_t)e * ED; }
    else        { s = d = e - EE;         eap = g_mean + (size_t)(e - EE) * ED; }
    float eav[ED];
#pragma unroll
    for (int j = 0; j < ED; j++) eav[j] = eap[j];
    float acc = 0.0f;
    for (int dd = lane; dd < dout; dd += 32) {
        float v = xl[(size_t)s * dout + dd] + xr[(size_t)d * dout + dd];
        float eed = 0.0f;
#pragma unroll
        for (int j = 0; j < ED; j++) eed += eav[j] * We[j * dout + dd];
        v += eed;
        v = v > 0.0f ? v : 0.2f * v;
        acc += att[dd] * v;
    }
#pragma unroll
    for (int o = 16; o; o >>= 1) acc += __shfl_down_sync(0xffffffffu, acc, o);
    if (lane == 0) g_alpha[e] = acc;
}

__global__ void k_amax(const int* __restrict__ dst) {
    int e = blockIdx.x * blockDim.x + threadIdx.x;
    if (e >= EA) return;
    int d = (e < EE) ? dst[e] : (e - EE);
    atomicMax(&g_amax[d], fkey(g_alpha[e]));
}

__global__ void k_exp(const int* __restrict__ dst) {
    int e = blockIdx.x * blockDim.x + threadIdx.x;
    if (e >= EA) return;
    int d = (e < EE) ? dst[e] : (e - EE);
    float am = funkey(g_amax[d]);
    float exv = expf(g_alpha[e] - am);
    g_ex[e] = exv;
    atomicAdd(&g_den[d], exv);
}

__global__ void k_bias(float* __restrict__ hn, const float* __restrict__ b, int dout) {
    int idx = blockIdx.x * blockDim.x + threadIdx.x;
    if (idx >= NN * dout) return;
    hn[idx] = b[idx % dout];
}

__global__ void k_agg(const int* __restrict__ src, const int* __restrict__ dst,
                      const float* __restrict__ xl, float* __restrict__ hn, int dout) {
    int e = (blockIdx.x * blockDim.x + threadIdx.x) >> 5;
    int lane = threadIdx.x & 31;
    if (e >= EA) return;
    int s, d;
    if (e < EE) { s = src[e]; d = dst[e]; }
    else        { s = d = e - EE; }
    float w = g_ex[e] / fmaxf(g_den[d], 1e-16f);
    for (int dd = lane; dd < dout; dd += 32)
        atomicAdd(&hn[(size_t)d * dout + dd], xl[(size_t)s * dout + dd] * w);
}

__global__ void k_relu(float* __restrict__ h, int n) {
    int idx = blockIdx.x * blockDim.x + threadIdx.x;
    if (idx < n) h[idx] = fmaxf(h[idx], 0.0f);
}

// ---------------- pack Wbi[k,i,j] -> U[i, k*16+j] (i<512), V (i>=512) ----------------
__global__ void k_pack(const float* __restrict__ Wbi) {
    int idx = blockIdx.x * blockDim.x + threadIdx.x;
    if (idx >= HMAX * CBI) return;
    int i = idx / CBI, c = idx % CBI;
    int k = c >> 4, j = c & 15;
    g_U[idx] = Wbi[((size_t)k * 1024 + i) * 16 + j];
    g_V[idx] = Wbi[((size_t)k * 1024 + 512 + i) * 16 + j];
}

// ---------------- fused edge scorer: bi -> MLP -> sigmoid; 8 edges per block ----------------
__global__ void k_score(const int* __restrict__ src, const int* __restrict__ dst,
                        const float* __restrict__ ea,
                        const float* __restrict__ bbi,
                        const float* __restrict__ Wm1, const float* __restrict__ bm1,
                        const float* __restrict__ Wm2, const float* __restrict__ bm2,
                        const float* __restrict__ Wm3, const float* __restrict__ bm3,
                        float* __restrict__ out) {
    __shared__ float s_bi[8][KBI];
    __shared__ float s_m1[8][KBI];
    __shared__ float s_m2[8][32];
    int tid = threadIdx.x, w = tid >> 5, lane = tid & 31;
    int e0 = blockIdx.x * 8;
    int e = e0 + w;
    if (e < EE) {
        int s = src[e], d = dst[e];
        int j = lane & 15;
        float eaj = ea[(size_t)e * ED + j];
        const float* Ap = g_A + (size_t)s * CBI;
        const float* Bp = g_B + (size_t)d * CBI;
        for (int it = 0; it < 136; it++) {
            int idx = it * 32 + lane;  // = k*16 + j, k = it*2 + lane/16
            float v = (Ap[idx] + Bp[idx]) * eaj;
            v += __shfl_down_sync(0xffffffffu, v, 8);
            v += __shfl_down_sync(0xffffffffu, v, 4);
            v += __shfl_down_sync(0xffffffffu, v, 2);
            v += __shfl_down_sync(0xffffffffu, v, 1);
            if (j == 0) {
                int k = it * 2 + (lane >> 4);
                s_bi[w][k] = v + bbi[k];
            }
        }
    } else {
        for (int k = lane; k < KBI; k += 32) s_bi[w][k] = 0.0f;
    }
    __syncthreads();
    // m1 = relu(bi @ Wm1 + bm1)   [272]
    for (int o = tid; o < KBI; o += 256) {
        float acc[8];
        float bv = bm1[o];
#pragma unroll
        for (int q = 0; q < 8; q++) acc[q] = bv;
        for (int k = 0; k < KBI; k++) {
            float wv = Wm1[(size_t)k * KBI + o];
#pragma unroll
            for (int q = 0; q < 8; q++) acc[q] += s_bi[q][k] * wv;
        }
#pragma unroll
        for (int q = 0; q < 8; q++) s_m1[q][o] = fmaxf(acc[q], 0.0f);
    }
    __syncthreads();
    // m2 = relu(m1 @ Wm2 + bm2)   [32]
    {
        int o = tid & 31, q = tid >> 5;
        float acc = bm2[o];
        for (int k = 0; k < KBI; k++) acc += s_m1[q][k] * Wm2[(size_t)k * 32 + o];
        s_m2[q][o] = fmaxf(acc, 0.0f);
    }
    __syncthreads();
    if (e < EE) {
        float p = s_m2[w][lane] * Wm3[lane];
#pragma unroll
        for (int o = 16; o; o >>= 1) p += __shfl_down_sync(0xffffffffu, p, o);
        if (lane == 0) out[e] = 1.0f / (1.0f + expf(-(p + bm3[0])));
    }
}

// ---------------- host ----------------
static inline dim3 gemm_grid(int M, int Nn) { return dim3(Nn / 128, (M + 127) / 128); }

extern "C" void kernel_launch(void* const* d_in, const int* in_sizes, int n_in,
                              void* d_out, int out_size) {
    const float* x         = (const float*)d_in[0];
    const float* edge_attr = (const float*)d_in[1];
    const int*   eidx      = (const int*)d_in[2];
    const int* src = eidx;
    const int* dst = eidx + EE;
    const float *Wl[4], *Wr[4], *We[4], *att[4], *bb[4];
    for (int l = 0; l < 4; l++) {
        int base = 3 + l * 5;
        Wl[l]  = (const float*)d_in[base + 0];
        Wr[l]  = (const float*)d_in[base + 1];
        We[l]  = (const float*)d_in[base + 2];
        att[l] = (const float*)d_in[base + 3];
        bb[l]  = (const float*)d_in[base + 4];
    }
    const float* Wbi = (const float*)d_in[23];
    const float* bbi = (const float*)d_in[24];
    const float* Wm1 = (const float*)d_in[25];
    const float* bm1 = (const float*)d_in[26];
    const float* Wm2 = (const float*)d_in[27];
    const float* bm2 = (const float*)d_in[28];
    const float* Wm3 = (const float*)d_in[29];
    const float* bm3 = (const float*)d_in[30];
    float* out = (float*)d_out;

    // scratch pointers
    float *h1, *h2, *xl, *xr, *U, *V, *A, *B, *den, *cnt, *msum;
    unsigned* amax;
    cudaGetSymbolAddress((void**)&h1, g_h1);
    cudaGetSymbolAddress((void**)&h2, g_h2);
    cudaGetSymbolAddress((void**)&xl, g_xl);
    cudaGetSymbolAddress((void**)&xr, g_xr);
    cudaGetSymbolAddress((void**)&U, g_U);
    cudaGetSymbolAddress((void**)&V, g_V);
    cudaGetSymbolAddress((void**)&A, g_A);
    cudaGetSymbolAddress((void**)&B, g_B);
    cudaGetSymbolAddress((void**)&den, g_den);
    cudaGetSymbolAddress((void**)&cnt, g_cnt);
    cudaGetSymbolAddress((void**)&msum, g_msum);
    cudaGetSymbolAddress((void**)&amax, g_amax);

    // edge_attr mean for self loops
    cudaMemsetAsync(cnt, 0, NN * sizeof(float));
    cudaMemsetAsync(msum, 0, NN * ED * sizeof(float));
    k_count<<<(EE * ED + 255) / 256, 256>>>(dst, edge_attr);
    k_mean<<<(NN * ED + 255) / 256, 256>>>();

    const float* hcur = x;
    int din = 32;
    float* hbufs[2] = { h1, h2 };
    const int warps_grid = (EA * 32 + 255) / 256;
    const int ea_grid = (EA + 255) / 256;

    for (int l = 0; l < 4; l++) {
        int dout = (l == 0) ? 256 : 512;
        sgemm128<<<gemm_grid(NN, dout), 256>>>(hcur, Wl[l], xl, NN, dout, din);
        sgemm128<<<gemm_grid(NN, dout), 256>>>(hcur, Wr[l], xr, NN, dout, din);
        cudaMemsetAsync(amax, 0, NN * sizeof(unsigned));
        cudaMemsetAsync(den, 0, NN * sizeof(float));
        k_alpha<<<warps_grid, 256>>>(src, dst, edge_attr, xl, xr, We[l], att[l], dout);
        k_amax<<<ea_grid, 256>>>(dst);
        k_exp<<<ea_grid, 256>>>(dst);
        float* hn = hbufs[l & 1];
        k_bias<<<(NN * dout + 255) / 256, 256>>>(hn, bb[l], dout);
        k_agg<<<warps_grid, 256>>>(src, dst, xl, hn, dout);
        if (l < 3) k_relu<<<(NN * dout + 255) / 256, 256>>>(hn, NN * dout);
        hcur = hn;
        din = dout;
    }

    // edge scoring
    k_pack<<<(HMAX * CBI + 255) / 256, 256>>>(Wbi);
    sgemm128<<<gemm_grid(NN, CBI), 256>>>(hcur, U, A, NN, CBI, HMAX);
    sgemm128<<<gemm_grid(NN, CBI), 256>>>(hcur, V, B, NN, CBI, HMAX);
    k_score<<<(EE + 7) / 8, 256>>>(src, dst, edge_attr, bbi, Wm1, bm1, Wm2, bm2, Wm3, bm3, out);
}

// round 4
// speedup vs baseline: 1.7530x; 1.7530x over previous
#include <cuda_runtime.h>
#include <cuda_bf16.h>
#include <math.h>

#define NN 10000
#define EE 50000
#define EA 60000      // E + N self loops
#define ED 16
#define KBI 272
#define CBI 4352      // 272*16
#define HMAX 512

// ---------------- scratch (static device globals; no runtime alloc) ----------------
__device__ float g_h1[NN * HMAX];
__device__ float g_h2[NN * HMAX];
__device__ float g_xl[NN * HMAX];
__device__ float g_xr[NN * HMAX];
__device__ float g_alpha[EA];
__device__ float g_ex[EA];
__device__ unsigned g_amax[NN];
__device__ float g_den[NN];
__device__ float g_cnt[NN];
__device__ float g_msum[NN * ED];
__device__ float g_mean[NN * ED];
__device__ float g_U[HMAX * CBI];
__device__ float g_V[HMAX * CBI];
__device__ float g_A[(size_t)NN * CBI];
__device__ float g_B[(size_t)NN * CBI];

// ---------------- helpers ----------------
__device__ __forceinline__ unsigned fkey(float f) {
    unsigned u = __float_as_uint(f);
    return (u & 0x80000000u) ? ~u : (u | 0x80000000u);
}
__device__ __forceinline__ float funkey(unsigned k) {
    return (k & 0x80000000u) ? __uint_as_float(k ^ 0x80000000u) : __uint_as_float(~k);
}
__device__ __forceinline__ unsigned to_tf32(float f) {
    unsigned r;
    asm("cvt.rna.tf32.f32 %0, %1;" : "=r"(r) : "f"(f));
    return r;
}

// ---------------- edge_attr mean per dst (self-loop fill 'mean') ----------------
__global__ void k_count(const int* __restrict__ dst, const float* __restrict__ ea) {
    int idx = blockIdx.x * blockDim.x + threadIdx.x;
    if (idx >= EE * ED) return;
    int e = idx >> 4, j = idx & 15;
    int d = dst[e];
    atomicAdd(&g_msum[d * ED + j], ea[idx]);
    if (j == 0) atomicAdd(&g_cnt[d], 1.0f);
}
__global__ void k_mean() {
    int idx = blockIdx.x * blockDim.x + threadIdx.x;
    if (idx >= NN * ED) return;
    g_mean[idx] = g_msum[idx] / fmaxf(g_cnt[idx >> 4], 1.0f);
}

// ---------------- TF32 tensor-core GEMM: C[M,N] = A[M,K] * B[K,N], row-major ----------------
// BM=BN=128, BK=16, 256 threads = 8 warps (4 in M x 2 in N), warp tile 32x64.
// mma.sync.aligned.m16n8k8.row.col.f32.tf32.tf32.f32
// Requires: N % 128 == 0, K % 16 == 0. M arbitrary (guarded).
__global__ __launch_bounds__(256) void tf32gemm(
        const float* __restrict__ A, const float* __restrict__ Bm,
        float* __restrict__ C, int M, int N, int K) {
    __shared__ unsigned As[16][132];   // [k][m], padded
    __shared__ unsigned Bs[16][132];   // [k][n], padded

    int tid = threadIdx.x;
    int lane = tid & 31, wid = tid >> 5;
    int g = lane >> 2, t = lane & 3;
    int wm = (wid & 3) * 32;           // warp row offset within block
    int wn = (wid >> 2) * 64;          // warp col offset within block
    int brow = blockIdx.y * 128;
    int bcol = blockIdx.x * 128;

    float c[2][8][4];
#pragma unroll
    for (int mi = 0; mi < 2; mi++)
#pragma unroll
        for (int nf = 0; nf < 8; nf++)
#pragma unroll
            for (int q = 0; q < 4; q++) c[mi][nf][q] = 0.0f;

    // A load: each thread 2 x float4 (rows arow, arow+64)
    int arow = tid >> 2;               // 0..63
    int akc  = (tid & 3) * 4;          // 0,4,8,12
    // B load: each thread 2 x float4
    int bkr  = tid >> 4;               // 0..15
    int bcc  = (tid & 15) * 8;         // 0..120

    for (int k0 = 0; k0 < K; k0 += 16) {
#pragma unroll
        for (int h = 0; h < 2; h++) {
            int r = arow + h * 64;
            float4 v = make_float4(0.f, 0.f, 0.f, 0.f);
            if (brow + r < M)
                v = *(const float4*)(A + (size_t)(brow + r) * K + k0 + akc);
            As[akc + 0][r] = to_tf32(v.x);
            As[akc + 1][r] = to_tf32(v.y);
            As[akc + 2][r] = to_tf32(v.z);
            As[akc + 3][r] = to_tf32(v.w);
        }
#pragma unroll
        for (int h = 0; h < 2; h++) {
            float4 v = *(const float4*)(Bm + (size_t)(k0 + bkr) * N + bcol + bcc + h * 4);
            Bs[bkr][bcc + h * 4 + 0] = to_tf32(v.x);
            Bs[bkr][bcc + h * 4 + 1] = to_tf32(v.y);
            Bs[bkr][bcc + h * 4 + 2] = to_tf32(v.z);
            Bs[bkr][bcc + h * 4 + 3] = to_tf32(v.w);
        }
        __syncthreads();
#pragma unroll
        for (int kk = 0; kk < 16; kk += 8) {
            unsigned a[2][4], b[8][2];
#pragma unroll
            for (int mi = 0; mi < 2; mi++) {
                int row = wm + mi * 16 + g;
                a[mi][0] = As[kk + t][row];
                a[mi][1] = As[kk + t][row + 8];
                a[mi][2] = As[kk + t + 4][row];
                a[mi][3] = As[kk + t + 4][row + 8];
            }
#pragma unroll
            for (int nf = 0; nf < 8; nf++) {
                int col = wn + nf * 8 + g;
                b[nf][0] = Bs[kk + t][col];
                b[nf][1] = Bs[kk + t + 4][col];
            }
#pragma unroll
            for (int mi = 0; mi < 2; mi++)
#pragma unroll
                for (int nf = 0; nf < 8; nf++) {
                    asm volatile(
                        "mma.sync.aligned.m16n8k8.row.col.f32.tf32.tf32.f32 "
                        "{%0,%1,%2,%3}, {%4,%5,%6,%7}, {%8,%9}, {%0,%1,%2,%3};"
                        : "+f"(c[mi][nf][0]), "+f"(c[mi][nf][1]),
                          "+f"(c[mi][nf][2]), "+f"(c[mi][nf][3])
                        : "r"(a[mi][0]), "r"(a[mi][1]), "r"(a[mi][2]), "r"(a[mi][3]),
                          "r"(b[nf][0]), "r"(b[nf][1]));
                }
        }
        __syncthreads();
    }

    // epilogue
#pragma unroll
    for (int mi = 0; mi < 2; mi++) {
        int row0 = brow + wm + mi * 16 + g;
#pragma unroll
        for (int nf = 0; nf < 8; nf++) {
            int col = bcol + wn + nf * 8 + 2 * t;
            if (row0 < M)
                *(float2*)(C + (size_t)row0 * N + col) = make_float2(c[mi][nf][0], c[mi][nf][1]);
            if (row0 + 8 < M)
                *(float2*)(C + (size_t)(row0 + 8) * N + col) = make_float2(c[mi][nf][2], c[mi][nf][3]);
        }
    }
}

// ---------------- GAT per-edge attention score (one warp per augmented edge) ----------------
__global__ void k_alpha(const int* __restrict__ src, const int* __restrict__ dst,
                        const float* __restrict__ ea,
                        const float* __restrict__ xl, const float* __restrict__ xr,
                        const float* __restrict__ We, const float* __restrict__ att,
                        int dout) {
    int e = (blockIdx.x * blockDim.x + threadIdx.x) >> 5;
    int lane = threadIdx.x & 31;
    if (e >= EA) return;
    int s, d;
    const float* eap;
    if (e < EE) { s = src[e]; d = dst[e]; eap = ea + (size_t)e * ED; }
    else        { s = d = e - EE;         eap = g_mean + (size_t)(e - EE) * ED; }
    float eav[ED];
#pragma unroll
    for (int j = 0; j < ED; j++) eav[j] = eap[j];
    float acc = 0.0f;
    for (int dd = lane; dd < dout; dd += 32) {
        float v = xl[(size_t)s * dout + dd] + xr[(size_t)d * dout + dd];
        float eed = 0.0f;
#pragma unroll
        for (int j = 0; j < ED; j++) eed += eav[j] * We[j * dout + dd];
        v += eed;
        v = v > 0.0f ? v : 0.2f * v;
        acc += att[dd] * v;
    }
#pragma unroll
    for (int o = 16; o; o >>= 1) acc += __shfl_down_sync(0xffffffffu, acc, o);
    if (lane == 0) {
        g_alpha[e] = acc;
        atomicMax(&g_amax[d], fkey(acc));
    }
}

__global__ void k_exp(const int* __restrict__ dst) {
    int e = blockIdx.x * blockDim.x + threadIdx.x;
    if (e >= EA) return;
    int d = (e < EE) ? dst[e] : (e - EE);
    float am = funkey(g_amax[d]);
    float exv = expf(g_alpha[e] - am);
    g_ex[e] = exv;
    atomicAdd(&g_den[d], exv);
}

__global__ void k_bias(float* __restrict__ hn, const float* __restrict__ b, int dout) {
    int idx = blockIdx.x * blockDim.x + threadIdx.x;
    if (idx >= NN * dout) return;
    hn[idx] = b[idx % dout];
}

__global__ void k_agg(const int* __restrict__ src, const int* __restrict__ dst,
                      const float* __restrict__ xl, float* __restrict__ hn, int dout) {
    int e = (blockIdx.x * blockDim.x + threadIdx.x) >> 5;
    int lane = threadIdx.x & 31;
    if (e >= EA) return;
    int s, d;
    if (e < EE) { s = src[e]; d = dst[e]; }
    else        { s = d = e - EE; }
    float w = g_ex[e] / fmaxf(g_den[d], 1e-16f);
    for (int dd = lane; dd < dout; dd += 32)
        atomicAdd(&hn[(size_t)d * dout + dd], xl[(size_t)s * dout + dd] * w);
}

__global__ void k_relu(float* __restrict__ h, int n) {
    int idx = blockIdx.x * blockDim.x + threadIdx.x;
    if (idx < n) h[idx] = fmaxf(h[idx], 0.0f);
}

// ---------------- pack Wbi[k,i,j] -> U[i, k*16+j] (i<512), V (i>=512) ----------------
__global__ void k_pack(const float* __restrict__ Wbi) {
    int idx = blockIdx.x * blockDim.x + threadIdx.x;
    if (idx >= HMAX * CBI) return;
    int i = idx / CBI, c = idx % CBI;
    int k = c >> 4, j = c & 15;
    g_U[idx] = Wbi[((size_t)k * 1024 + i) * 16 + j];
    g_V[idx] = Wbi[((size_t)k * 1024 + 512 + i) * 16 + j];
}

// ---------------- fused edge scorer: bi -> MLP -> sigmoid; 8 edges per block ----------------
__global__ void k_score(const int* __restrict__ src, const int* __restrict__ dst,
                        const float* __restrict__ ea,
                        const float* __restrict__ bbi,
                        const float* __restrict__ Wm1, const float* __restrict__ bm1,
                        const float* __restrict__ Wm2, const float* __restrict__ bm2,
                        const float* __restrict__ Wm3, const float* __restrict__ bm3,
                        float* __restrict__ out) {
    __shared__ float s_bi[8][KBI];
    __shared__ float s_m1[8][KBI];
    __shared__ float s_m2[8][32];
    int tid = threadIdx.x, w = tid >> 5, lane = tid & 31;
    int e0 = blockIdx.x * 8;
    int e = e0 + w;
    if (e < EE) {
        int s = src[e], d = dst[e];
        int j = lane & 15;
        float eaj = ea[(size_t)e * ED + j];
        const float* Ap = g_A + (size_t)s * CBI;
        const float* Bp = g_B + (size_t)d * CBI;
        for (int it = 0; it < 136; it++) {
            int idx = it * 32 + lane;  // = k*16 + j, k = it*2 + lane/16
            float v = (Ap[idx] + Bp[idx]) * eaj;
            v += __shfl_down_sync(0xffffffffu, v, 8);
            v += __shfl_down_sync(0xffffffffu, v, 4);
            v += __shfl_down_sync(0xffffffffu, v, 2);
            v += __shfl_down_sync(0xffffffffu, v, 1);
            if (j == 0) {
                int k = it * 2 + (lane >> 4);
                s_bi[w][k] = v + bbi[k];
            }
        }
    } else {
        for (int k = lane; k < KBI; k += 32) s_bi[w][k] = 0.0f;
    }
    __syncthreads();
    // m1 = relu(bi @ Wm1 + bm1)   [272]
    for (int o = tid; o < KBI; o += 256) {
        float acc[8];
        float bv = bm1[o];
#pragma unroll
        for (int q = 0; q < 8; q++) acc[q] = bv;
        for (int k = 0; k < KBI; k++) {
            float wv = Wm1[(size_t)k * KBI + o];
#pragma unroll
            for (int q = 0; q < 8; q++) acc[q] += s_bi[q][k] * wv;
        }
#pragma unroll
        for (int q = 0; q < 8; q++) s_m1[q][o] = fmaxf(acc[q], 0.0f);
    }
    __syncthreads();
    // m2 = relu(m1 @ Wm2 + bm2)   [32]
    {
        int o = tid & 31, q = tid >> 5;
        float acc = bm2[o];
        for (int k = 0; k < KBI; k++) acc += s_m1[q][k] * Wm2[(size_t)k * 32 + o];
        s_m2[q][o] = fmaxf(acc, 0.0f);
    }
    __syncthreads();
    if (e < EE) {
        float p = s_m2[w][lane] * Wm3[lane];
#pragma unroll
        for (int o = 16; o; o >>= 1) p += __shfl_down_sync(0xffffffffu, p, o);
        if (lane == 0) out[e] = 1.0f / (1.0f + expf(-(p + bm3[0])));
    }
}

// ---------------- host ----------------
static inline dim3 gemm_grid(int M, int Nn) { return dim3(Nn / 128, (M + 127) / 128); }

extern "C" void kernel_launch(void* const* d_in, const int* in_sizes, int n_in,
                              void* d_out, int out_size) {
    const float* x         = (const float*)d_in[0];
    const float* edge_attr = (const float*)d_in[1];
    const int*   eidx      = (const int*)d_in[2];
    const int* src = eidx;
    const int* dst = eidx + EE;
    const float *Wl[4], *Wr[4], *We[4], *att[4], *bb[4];
    for (int l = 0; l < 4; l++) {
        int base = 3 + l * 5;
        Wl[l]  = (const float*)d_in[base + 0];
        Wr[l]  = (const float*)d_in[base + 1];
        We[l]  = (const float*)d_in[base + 2];
        att[l] = (const float*)d_in[base + 3];
        bb[l]  = (const float*)d_in[base + 4];
    }
    const float* Wbi = (const float*)d_in[23];
    const float* bbi = (const float*)d_in[24];
    const float* Wm1 = (const float*)d_in[25];
    const float* bm1 = (const float*)d_in[26];
    const float* Wm2 = (const float*)d_in[27];
    const float* bm2 = (const float*)d_in[28];
    const float* Wm3 = (const float*)d_in[29];
    const float* bm3 = (const float*)d_in[30];
    float* out = (float*)d_out;

    // scratch pointers
    float *h1, *h2, *xl, *xr, *U, *V, *A, *B, *den, *cnt, *msum;
    unsigned* amax;
    cudaGetSymbolAddress((void**)&h1, g_h1);
    cudaGetSymbolAddress((void**)&h2, g_h2);
    cudaGetSymbolAddress((void**)&xl, g_xl);
    cudaGetSymbolAddress((void**)&xr, g_xr);
    cudaGetSymbolAddress((void**)&U, g_U);
    cudaGetSymbolAddress((void**)&V, g_V);
    cudaGetSymbolAddress((void**)&A, g_A);
    cudaGetSymbolAddress((void**)&B, g_B);
    cudaGetSymbolAddress((void**)&den, g_den);
    cudaGetSymbolAddress((void**)&cnt, g_cnt);
    cudaGetSymbolAddress((void**)&msum, g_msum);
    cudaGetSymbolAddress((void**)&amax, g_amax);

    // edge_attr mean for self loops
    cudaMemsetAsync(cnt, 0, NN * sizeof(float));
    cudaMemsetAsync(msum, 0, NN * ED * sizeof(float));
    k_count<<<(EE * ED + 255) / 256, 256>>>(dst, edge_attr);
    k_mean<<<(NN * ED + 255) / 256, 256>>>();

    const float* hcur = x;
    int din = 32;
    float* hbufs[2] = { h1, h2 };
    const int warps_grid = (EA * 32 + 255) / 256;
    const int ea_grid = (EA + 255) / 256;

    for (int l = 0; l < 4; l++) {
        int dout = (l == 0) ? 256 : 512;
        cudaMemsetAsync(amax, 0, NN * sizeof(unsigned));
        cudaMemsetAsync(den, 0, NN * sizeof(float));
        tf32gemm<<<gemm_grid(NN, dout), 256>>>(hcur, Wl[l], xl, NN, dout, din);
        tf32gemm<<<gemm_grid(NN, dout), 256>>>(hcur, Wr[l], xr, NN, dout, din);
        k_alpha<<<warps_grid, 256>>>(src, dst, edge_attr, xl, xr, We[l], att[l], dout);
        k_exp<<<ea_grid, 256>>>(dst);
        float* hn = hbufs[l & 1];
        k_bias<<<(NN * dout + 255) / 256, 256>>>(hn, bb[l], dout);
        k_agg<<<warps_grid, 256>>>(src, dst, xl, hn, dout);
        if (l < 3) k_relu<<<(NN * dout + 255) / 256, 256>>>(hn, NN * dout);
        hcur = hn;
        din = dout;
    }

    // edge scoring
    k_pack<<<(HMAX * CBI + 255) / 256, 256>>>(Wbi);
    tf32gemm<<<gemm_grid(NN, CBI), 256>>>(hcur, U, A, NN, CBI, HMAX);
    tf32gemm<<<gemm_grid(NN, CBI), 256>>>(hcur, V, B, NN, CBI, HMAX);
    k_score<<<(EE + 7) / 8, 256>>>(src, dst, edge_attr, bbi, Wm1, bm1, Wm2, bm2, Wm3, bm3, out);
}

// round 5
// speedup vs baseline: 2.0321x; 1.1592x over previous
#include <cuda_runtime.h>
#include <cuda_bf16.h>
#include <math.h>
#include <stdint.h>

#define NN 10000
#define EE 50000
#define EA 60000      // E + N self loops
#define ED 16
#define KBI 272
#define CBI 4352      // 272*16
#define HMAX 512

// ---------------- scratch (static device globals; no runtime alloc) ----------------
__device__ float g_h1[NN * HMAX];
__device__ float g_h2[NN * HMAX];
__device__ float g_xl[NN * HMAX];
__device__ float g_xr[NN * HMAX];
__device__ float g_alpha[EA];
__device__ float g_ex[EA];
__device__ unsigned g_amax[NN];
__device__ float g_den[NN];
__device__ float g_cnt[NN];
__device__ float g_msum[NN * ED];
__device__ float g_mean[NN * ED];
__device__ float g_U[HMAX * CBI];
__device__ float g_V[HMAX * CBI];
__device__ float g_A[(size_t)NN * CBI];
__device__ float g_B[(size_t)NN * CBI];

// ---------------- helpers ----------------
__device__ __forceinline__ unsigned fkey(float f) {
    unsigned u = __float_as_uint(f);
    return (u & 0x80000000u) ? ~u : (u | 0x80000000u);
}
__device__ __forceinline__ float funkey(unsigned k) {
    return (k & 0x80000000u) ? __uint_as_float(k ^ 0x80000000u) : __uint_as_float(~k);
}
__device__ __forceinline__ uint32_t bfpair(float lo, float hi) {
    __nv_bfloat162 h2 = __floats2bfloat162_rn(lo, hi);
    return *reinterpret_cast<uint32_t*>(&h2);
}

// ---------------- edge_attr mean per dst (self-loop fill 'mean') ----------------
__global__ void k_count(const int* __restrict__ dst, const float* __restrict__ ea) {
    int idx = blockIdx.x * blockDim.x + threadIdx.x;
    if (idx >= EE * ED) return;
    int e = idx >> 4, j = idx & 15;
    int d = dst[e];
    atomicAdd(&g_msum[d * ED + j], ea[idx]);
    if (j == 0) atomicAdd(&g_cnt[d], 1.0f);
}
__global__ void k_mean() {
    int idx = blockIdx.x * blockDim.x + threadIdx.x;
    if (idx >= NN * ED) return;
    g_mean[idx] = g_msum[idx] / fmaxf(g_cnt[idx >> 4], 1.0f);
}

// ---------------- BF16 tensor-core GEMM: C[M,N] = A[M,K] * B[K,N], row-major fp32 in/out --
// BM=BN=128, BK=32, 256 threads = 8 warps (4 in M x 2 in N), warp tile 32x64.
// mma.sync.aligned.m16n8k16.row.col.f32.bf16.bf16.f32, fp32->bf16 convert in the load path.
// Double-buffered smem, register-staged global prefetch, 1 syncthreads per 32-K slab.
// Requires: N % 128 == 0, K % 32 == 0. M arbitrary (guarded).
__global__ __launch_bounds__(256) void bf16gemm(
        const float* __restrict__ A, const float* __restrict__ Bm,
        float* __restrict__ C, int M, int N, int K) {
    // uint32 element = bf16 pair {k even (low), k odd (high)}
    __shared__ uint32_t As[2][128][17];   // [buf][m][kpair], padded
    __shared__ uint32_t Bs[2][128][17];   // [buf][n][kpair], padded

    int tid = threadIdx.x;
    int lane = tid & 31, wid = tid >> 5;
    int g = lane >> 2, t = lane & 3;
    int wm = (wid & 3) * 32;
    int wn = (wid >> 2) * 64;
    int brow = blockIdx.y * 128;
    int bcol = blockIdx.x * 128;

    float c[2][8][4];
#pragma unroll
    for (int mi = 0; mi < 2; mi++)
#pragma unroll
        for (int nf = 0; nf < 8; nf++)
#pragma unroll
            for (int q = 0; q < 4; q++) c[mi][nf][q] = 0.0f;

    // A staging: thread covers row (tid>>1), cols half*16 .. +15 of the 32-wide slab
    int arow = tid >> 1;
    int ahalf = tid & 1;
    bool a_ok = (brow + arow) < M;
    const float* Aip = A + (size_t)(brow + arow) * K + ahalf * 16;
    // B staging: 2 tasks/thread; task: kpair kp=task>>5 (0..15), colgroup cg=task&31 (4 cols)
    float4 a4[4];
    float4 b4[2][2];

    auto load_regs = [&](int k0) {
#pragma unroll
        for (int q = 0; q < 4; q++)
            a4[q] = a_ok ? *(const float4*)(Aip + k0 + q * 4)
                         : make_float4(0.f, 0.f, 0.f, 0.f);
#pragma unroll
        for (int s = 0; s < 2; s++) {
            int task = tid + s * 256;
            int kp = task >> 5, cg = task & 31;
            const float* bp = Bm + (size_t)(k0 + 2 * kp) * N + bcol + cg * 4;
            b4[s][0] = *(const float4*)(bp);
            b4[s][1] = *(const float4*)(bp + N);
        }
    };
    auto store_smem = [&](int buf) {
#pragma unroll
        for (int p = 0; p < 8; p++) {
            const float* f = (const float*)&a4[0];
            As[buf][arow][ahalf * 8 + p] = bfpair(f[2 * p], f[2 * p + 1]);
        }
#pragma unroll
        for (int s = 0; s < 2; s++) {
            int task = tid + s * 256;
            int kp = task >> 5, cg = task & 31;
            const float* f0 = (const float*)&b4[s][0];
            const float* f1 = (const float*)&b4[s][1];
#pragma unroll
            for (int j = 0; j < 4; j++)
                Bs[buf][cg * 4 + j][kp] = bfpair(f0[j], f1[j]);
        }
    };

    load_regs(0);
    store_smem(0);
    __syncthreads();

    int buf = 0;
    for (int k0 = 0; k0 < K; k0 += 32) {
        bool nxt = (k0 + 32) < K;
        if (nxt) load_regs(k0 + 32);
#pragma unroll
        for (int ks = 0; ks < 2; ks++) {
            uint32_t a[2][4], b[8][2];
#pragma unroll
            for (int mi = 0; mi < 2; mi++) {
                int row = wm + mi * 16 + g;
                a[mi][0] = As[buf][row][ks * 8 + t];
                a[mi][1] = As[buf][row + 8][ks * 8 + t];
                a[mi][2] = As[buf][row][ks * 8 + t + 4];
                a[mi][3] = As[buf][row + 8][ks * 8 + t + 4];
            }
#pragma unroll
            for (int nf = 0; nf < 8; nf++) {
                int col = wn + nf * 8 + g;
                b[nf][0] = Bs[buf][col][ks * 8 + t];
                b[nf][1] = Bs[buf][col][ks * 8 + t + 4];
            }
#pragma unroll
            for (int mi = 0; mi < 2; mi++)
#pragma unroll
                for (int nf = 0; nf < 8; nf++) {
                    asm volatile(
                        "mma.sync.aligned.m16n8k16.row.col.f32.bf16.bf16.f32 "
                        "{%0,%1,%2,%3}, {%4,%5,%6,%7}, {%8,%9}, {%0,%1,%2,%3};"
                        : "+f"(c[mi][nf][0]), "+f"(c[mi][nf][1]),
                          "+f"(c[mi][nf][2]), "+f"(c[mi][nf][3])
                        : "r"(a[mi][0]), "r"(a[mi][1]), "r"(a[mi][2]), "r"(a[mi][3]),
                          "r"(b[nf][0]), "r"(b[nf][1]));
                }
        }
        if (nxt) {
            store_smem(buf ^ 1);
            __syncthreads();
            buf ^= 1;
        }
    }

    // epilogue
#pragma unroll
    for (int mi = 0; mi < 2; mi++) {
        int row0 = brow + wm + mi * 16 + g;
#pragma unroll
        for (int nf = 0; nf < 8; nf++) {
            int col = bcol + wn + nf * 8 + 2 * t;
            if (row0 < M)
                *(float2*)(C + (size_t)row0 * N + col) = make_float2(c[mi][nf][0], c[mi][nf][1]);
            if (row0 + 8 < M)
                *(float2*)(C + (size_t)(row0 + 8) * N + col) = make_float2(c[mi][nf][2], c[mi][nf][3]);
        }
    }
}

// ---------------- GAT per-edge attention score (one warp per augmented edge) ----------------
__global__ void k_alpha(const int* __restrict__ src, const int* __restrict__ dst,
                        const float* __restrict__ ea,
                        const float* __restrict__ xl, const float* __restrict__ xr,
                        const float* __restrict__ We, const float* __restrict__ att,
                        int dout) {
    int e = (blockIdx.x * blockDim.x + threadIdx.x) >> 5;
    int lane = threadIdx.x & 31;
    if (e >= EA) return;
    int s, d;
    const float* eap;
    if (e < EE) { s = src[e]; d = dst[e]; eap = ea + (size_t)e * ED; }
    else        { s = d = e - EE;         eap = g_mean + (size_t)(e - EE) * ED; }
    float eav[ED];
#pragma unroll
    for (int j = 0; j < ED; j++) eav[j] = eap[j];
    float acc = 0.0f;
    for (int dd = lane; dd < dout; dd += 32) {
        float v = xl[(size_t)s * dout + dd] + xr[(size_t)d * dout + dd];
        float eed = 0.0f;
#pragma unroll
        for (int j = 0; j < ED; j++) eed += eav[j] * We[j * dout + dd];
        v += eed;
        v = v > 0.0f ? v : 0.2f * v;
        acc += att[dd] * v;
    }
#pragma unroll
    for (int o = 16; o; o >>= 1) acc += __shfl_down_sync(0xffffffffu, acc, o);
    if (lane == 0) {
        g_alpha[e] = acc;
        atomicMax(&g_amax[d], fkey(acc));
    }
}

__global__ void k_exp(const int* __restrict__ dst) {
    int e = blockIdx.x * blockDim.x + threadIdx.x;
    if (e >= EA) return;
    int d = (e < EE) ? dst[e] : (e - EE);
    float am = funkey(g_amax[d]);
    float exv = expf(g_alpha[e] - am);
    g_ex[e] = exv;
    atomicAdd(&g_den[d], exv);
}

__global__ void k_bias(float* __restrict__ hn, const float* __restrict__ b, int dout) {
    int idx = blockIdx.x * blockDim.x + threadIdx.x;
    if (idx >= NN * dout) return;
    hn[idx] = b[idx % dout];
}

__global__ void k_agg(const int* __restrict__ src, const int* __restrict__ dst,
                      const float* __restrict__ xl, float* __restrict__ hn, int dout) {
    int e = (blockIdx.x * blockDim.x + threadIdx.x) >> 5;
    int lane = threadIdx.x & 31;
    if (e >= EA) return;
    int s, d;
    if (e < EE) { s = src[e]; d = dst[e]; }
    else        { s = d = e - EE; }
    float w = g_ex[e] / fmaxf(g_den[d], 1e-16f);
    for (int dd = lane; dd < dout; dd += 32)
        atomicAdd(&hn[(size_t)d * dout + dd], xl[(size_t)s * dout + dd] * w);
}

__global__ void k_relu(float* __restrict__ h, int n) {
    int idx = blockIdx.x * blockDim.x + threadIdx.x;
    if (idx < n) h[idx] = fmaxf(h[idx], 0.0f);
}

// ---------------- pack Wbi[k,i,j] -> U[i, k*16+j] (i<512), V (i>=512) ----------------
__global__ void k_pack(const float* __restrict__ Wbi) {
    int idx = blockIdx.x * blockDim.x + threadIdx.x;
    if (idx >= HMAX * CBI) return;
    int i = idx / CBI, c = idx % CBI;
    int k = c >> 4, j = c & 15;
    g_U[idx] = Wbi[((size_t)k * 1024 + i) * 16 + j];
    g_V[idx] = Wbi[((size_t)k * 1024 + 512 + i) * 16 + j];
}

// ---------------- fused edge scorer: bi -> MLP -> sigmoid; 8 edges per block ----------------
__global__ void k_score(const int* __restrict__ src, const int* __restrict__ dst,
                        const float* __restrict__ ea,
                        const float* __restrict__ bbi,
                        const float* __restrict__ Wm1, const float* __restrict__ bm1,
                        const float* __restrict__ Wm2, const float* __restrict__ bm2,
                        const float* __restrict__ Wm3, const float* __restrict__ bm3,
                        float* __restrict__ out) {
    __shared__ float s_bi[8][KBI];
    __shared__ float s_m1[8][KBI];
    __shared__ float s_m2[8][32];
    int tid = threadIdx.x, w = tid >> 5, lane = tid & 31;
    int e0 = blockIdx.x * 8;
    int e = e0 + w;
    if (e < EE) {
        int s = src[e], d = dst[e];
        int j = lane & 15;
        float eaj = ea[(size_t)e * ED + j];
        const float* Ap = g_A + (size_t)s * CBI;
        const float* Bp = g_B + (size_t)d * CBI;
        for (int it = 0; it < 136; it++) {
            int idx = it * 32 + lane;  // = k*16 + j, k = it*2 + lane/16
            float v = (Ap[idx] + Bp[idx]) * eaj;
            v += __shfl_down_sync(0xffffffffu, v, 8);
            v += __shfl_down_sync(0xffffffffu, v, 4);
            v += __shfl_down_sync(0xffffffffu, v, 2);
            v += __shfl_down_sync(0xffffffffu, v, 1);
            if (j == 0) {
                int k = it * 2 + (lane >> 4);
                s_bi[w][k] = v + bbi[k];
            }
        }
    } else {
        for (int k = lane; k < KBI; k += 32) s_bi[w][k] = 0.0f;
    }
    __syncthreads();
    // m1 = relu(bi @ Wm1 + bm1)   [272]
    for (int o = tid; o < KBI; o += 256) {
        float acc[8];
        float bv = bm1[o];
#pragma unroll
        for (int q = 0; q < 8; q++) acc[q] = bv;
        for (int k = 0; k < KBI; k++) {
            float wv = Wm1[(size_t)k * KBI + o];
#pragma unroll
            for (int q = 0; q < 8; q++) acc[q] += s_bi[q][k] * wv;
        }
#pragma unroll
        for (int q = 0; q < 8; q++) s_m1[q][o] = fmaxf(acc[q], 0.0f);
    }
    __syncthreads();
    // m2 = relu(m1 @ Wm2 + bm2)   [32]
    {
        int o = tid & 31, q = tid >> 5;
        float acc = bm2[o];
        for (int k = 0; k < KBI; k++) acc += s_m1[q][k] * Wm2[(size_t)k * 32 + o];
        s_m2[q][o] = fmaxf(acc, 0.0f);
    }
    __syncthreads();
    if (e < EE) {
        float p = s_m2[w][lane] * Wm3[lane];
#pragma unroll
        for (int o = 16; o; o >>= 1) p += __shfl_down_sync(0xffffffffu, p, o);
        if (lane == 0) out[e] = 1.0f / (1.0f + expf(-(p + bm3[0])));
    }
}

// ---------------- host ----------------
static inline dim3 gemm_grid(int M, int Nn) { return dim3(Nn / 128, (M + 127) / 128); }

extern "C" void kernel_launch(void* const* d_in, const int* in_sizes, int n_in,
                              void* d_out, int out_size) {
    const float* x         = (const float*)d_in[0];
    const float* edge_attr = (const float*)d_in[1];
    const int*   eidx      = (const int*)d_in[2];
    const int* src = eidx;
    const int* dst = eidx + EE;
    const float *Wl[4], *Wr[4], *We[4], *att[4], *bb[4];
    for (int l = 0; l < 4; l++) {
        int base = 3 + l * 5;
        Wl[l]  = (const float*)d_in[base + 0];
        Wr[l]  = (const float*)d_in[base + 1];
        We[l]  = (const float*)d_in[base + 2];
        att[l] = (const float*)d_in[base + 3];
        bb[l]  = (const float*)d_in[base + 4];
    }
    const float* Wbi = (const float*)d_in[23];
    const float* bbi = (const float*)d_in[24];
    const float* Wm1 = (const float*)d_in[25];
    const float* bm1 = (const float*)d_in[26];
    const float* Wm2 = (const float*)d_in[27];
    const float* bm2 = (const float*)d_in[28];
    const float* Wm3 = (const float*)d_in[29];
    const float* bm3 = (const float*)d_in[30];
    float* out = (float*)d_out;

    // scratch pointers
    float *h1, *h2, *xl, *xr, *U, *V, *A, *B, *den, *cnt, *msum;
    unsigned* amax;
    cudaGetSymbolAddress((void**)&h1, g_h1);
    cudaGetSymbolAddress((void**)&h2, g_h2);
    cudaGetSymbolAddress((void**)&xl, g_xl);
    cudaGetSymbolAddress((void**)&xr, g_xr);
    cudaGetSymbolAddress((void**)&U, g_U);
    cudaGetSymbolAddress((void**)&V, g_V);
    cudaGetSymbolAddress((void**)&A, g_A);
    cudaGetSymbolAddress((void**)&B, g_B);
    cudaGetSymbolAddress((void**)&den, g_den);
    cudaGetSymbolAddress((void**)&cnt, g_cnt);
    cudaGetSymbolAddress((void**)&msum, g_msum);
    cudaGetSymbolAddress((void**)&amax, g_amax);

    // edge_attr mean for self loops
    cudaMemsetAsync(cnt, 0, NN * sizeof(float));
    cudaMemsetAsync(msum, 0, NN * ED * sizeof(float));
    k_count<<<(EE * ED + 255) / 256, 256>>>(dst, edge_attr);
    k_mean<<<(NN * ED + 255) / 256, 256>>>();

    const float* hcur = x;
    int din = 32;
    float* hbufs[2] = { h1, h2 };
    const int warps_grid = (EA * 32 + 255) / 256;
    const int ea_grid = (EA + 255) / 256;

    for (int l = 0; l < 4; l++) {
        int dout = (l == 0) ? 256 : 512;
        cudaMemsetAsync(amax, 0, NN * sizeof(unsigned));
        cudaMemsetAsync(den, 0, NN * sizeof(float));
        bf16gemm<<<gemm_grid(NN, dout), 256>>>(hcur, Wl[l], xl, NN, dout, din);
        bf16gemm<<<gemm_grid(NN, dout), 256>>>(hcur, Wr[l], xr, NN, dout, din);
        k_alpha<<<warps_grid, 256>>>(src, dst, edge_attr, xl, xr, We[l], att[l], dout);
        k_exp<<<ea_grid, 256>>>(dst);
        float* hn = hbufs[l & 1];
        k_bias<<<(NN * dout + 255) / 256, 256>>>(hn, bb[l], dout);
        k_agg<<<warps_grid, 256>>>(src, dst, xl, hn, dout);
        if (l < 3) k_relu<<<(NN * dout + 255) / 256, 256>>>(hn, NN * dout);
        hcur = hn;
        din = dout;
    }

    // edge scoring
    k_pack<<<(HMAX * CBI + 255) / 256, 256>>>(Wbi);
    bf16gemm<<<gemm_grid(NN, CBI), 256>>>(hcur, U, A, NN, CBI, HMAX);
    bf16gemm<<<gemm_grid(NN, CBI), 256>>>(hcur, V, B, NN, CBI, HMAX);
    k_score<<<(EE + 7) / 8, 256>>>(src, dst, edge_attr, bbi, Wm1, bm1, Wm2, bm2, Wm3, bm3, out);
}